// round 17
// baseline (speedup 1.0000x reference)
#include <cuda_runtime.h>
#include <cuda_bf16.h>
#include <cuda_fp16.h>
#include <cstdint>

// ---------------------------------------------------------------------------
// SimpleSNN, emulated-fp32 GEMMs on mma.sync (sm_80+ family ISA).
// GEMM1 (at the legacy-HMMA wall ~170 TF/s): fp16 2-split
//   x = a1 + 2^-12*a2', W1 = b1 + 2^-12*b2'; products a1b2', a2'b1, a1b1;
//   corrections in one tensor chain (drained x2^-12 at kt=63); a1b1 drained
//   into SMEM fp32 masters every 2 chunks. 512 thr, warp tile 32x16, 2 CTA/SM.
// GEMM2: single fp16 product (spikes exact fp16 ints; W2 fp16 ~1e-4 on out).
// R17: vectorized split, 5-stage gemm1 pipeline, L2 cache-policy hints.
// d_out layout: [ output (B*OUT) | total_spikes (B*H) ]
// ---------------------------------------------------------------------------

#define BDIM 4096
#define INDIM 1024
#define HDIM 2048
#define ODIM 256

__device__ __half g_A1H[(size_t)BDIM * 2048];  // x   [a1|a2'*2^12]
__device__ __half g_B1H[(size_t)HDIM * 2048];  // W1  [b1|b2'*2^12]
__device__ __half g_SH [(size_t)BDIM * HDIM];  // spikes fp16 (exact)
__device__ __half g_W2H[(size_t)ODIM * HDIM];  // W2  fp16 (single)

// ------------------------------ helpers ------------------------------------
__device__ __forceinline__ uint32_t smem_u32(const void* p) {
    uint32_t a;
    asm("{ .reg .u64 t; cvta.to.shared.u64 t, %1; cvt.u32.u64 %0, t; }" : "=r"(a) : "l"(p));
    return a;
}
#define CP16(dst, src)  asm volatile("cp.async.cg.shared.global [%0], [%1], 16;" :: "r"(dst), "l"(src))
#define CP_COMMIT()     asm volatile("cp.async.commit_group;" ::: "memory")
#define CP_WAIT3()      asm volatile("cp.async.wait_group 3;" ::: "memory")
#define CP_WAIT2()      asm volatile("cp.async.wait_group 2;" ::: "memory")
#define LDSM4(R, a) asm volatile("ldmatrix.sync.aligned.m8n8.x4.shared.b16 {%0,%1,%2,%3}, [%4];" \
    : "=r"((R)[0]), "=r"((R)[1]), "=r"((R)[2]), "=r"((R)[3]) : "r"(a))

__device__ __forceinline__ void mma_f16(float* c, const uint32_t* a, const uint32_t* b) {
    asm volatile(
        "mma.sync.aligned.m16n8k16.row.col.f32.f16.f16.f32 "
        "{%0,%1,%2,%3}, {%4,%5,%6,%7}, {%8,%9}, {%0,%1,%2,%3};"
        : "+f"(c[0]), "+f"(c[1]), "+f"(c[2]), "+f"(c[3])
        : "r"(a[0]), "r"(a[1]), "r"(a[2]), "r"(a[3]), "r"(b[0]), "r"(b[1]));
}

__device__ __forceinline__ uint32_t pack2(__half a, __half b) {
    __half2 t; t.x = a; t.y = b;
    return *reinterpret_cast<uint32_t*>(&t);
}

// --------------------------- fused split kernel (vectorized) ----------------
__global__ void split_all_kernel(const float* __restrict__ x,
                                 const float* __restrict__ W1,
                                 const float* __restrict__ W2)
{
    const int stride = gridDim.x * blockDim.x;
    const int t0 = blockIdx.x * blockDim.x + threadIdx.x;
    // x: [BDIM,1024] -> g_A1H [BDIM,2048]; 4 elems/iter
    for (int e4 = t0; e4 < (BDIM * INDIM) / 4; e4 += stride) {
        const int r = e4 >> 8, k = (e4 & 255) * 4;
        const float4 v = reinterpret_cast<const float4*>(x)[e4];
        __half h1[4], h2[4];
        const float* vf = &v.x;
#pragma unroll
        for (int j = 0; j < 4; j++) {
            h1[j] = __float2half_rn(vf[j]);
            h2[j] = __float2half_rn((vf[j] - __half2float(h1[j])) * 4096.0f);
        }
        __half* d = g_A1H + (size_t)r * 2048;
        uint2 u1; u1.x = pack2(h1[0], h1[1]); u1.y = pack2(h1[2], h1[3]);
        uint2 u2; u2.x = pack2(h2[0], h2[1]); u2.y = pack2(h2[2], h2[3]);
        *reinterpret_cast<uint2*>(d + k)        = u1;
        *reinterpret_cast<uint2*>(d + 1024 + k) = u2;
    }
    // W1: [HDIM,1024] -> g_B1H
    for (int e4 = t0; e4 < (HDIM * INDIM) / 4; e4 += stride) {
        const int r = e4 >> 8, k = (e4 & 255) * 4;
        const float4 v = reinterpret_cast<const float4*>(W1)[e4];
        __half h1[4], h2[4];
        const float* vf = &v.x;
#pragma unroll
        for (int j = 0; j < 4; j++) {
            h1[j] = __float2half_rn(vf[j]);
            h2[j] = __float2half_rn((vf[j] - __half2float(h1[j])) * 4096.0f);
        }
        __half* d = g_B1H + (size_t)r * 2048;
        uint2 u1; u1.x = pack2(h1[0], h1[1]); u1.y = pack2(h1[2], h1[3]);
        uint2 u2; u2.x = pack2(h2[0], h2[1]); u2.y = pack2(h2[2], h2[3]);
        *reinterpret_cast<uint2*>(d + k)        = u1;
        *reinterpret_cast<uint2*>(d + 1024 + k) = u2;
    }
    // W2: [ODIM,2048] -> g_W2H fp16 single
    for (int e4 = t0; e4 < (ODIM * HDIM) / 4; e4 += stride) {
        const float4 v = reinterpret_cast<const float4*>(W2)[e4];
        uint2 u; u.x = pack2(__float2half_rn(v.x), __float2half_rn(v.y));
        u.y = pack2(__float2half_rn(v.z), __float2half_rn(v.w));
        *reinterpret_cast<uint2*>(g_W2H + e4 * 4) = u;
    }
}

// ------------------------------ GEMM1 + LIF --------------------------------
// CTA 128(M)x64(N), 512 threads, warp grid 4(m)x4(n), warp tile 32x16.
// BK=32 fp16 (64B rows padded to 80B), 5-stage cp.async, wait_group 3.
// smem: 5x(10240+5120) + 32KB masters = 109568 B -> 2 CTAs/SM, 32 warps.
// 96 chunks = 3 products x 32:
//   p0 (0-31):  a1  x b2'   } corrections, one chain, drained x2^-12 at kt=63
//   p1 (32-63): a2' x b1    }
//   p2 (64-95): a1  x b1    — drained into smem masters every 2 chunks
#define G1_CHUNKS 96
#define G1_STAGES 5
#define RB1 80                // bytes per smem row
#define AST1 (128 * RB1)      // 10240 B per A stage
#define BST1 (64 * RB1)       // 5120 B per B stage
#define SMEM1 (G1_STAGES * (AST1 + BST1) + 512 * 16 * 4)   // 109568

__device__ __forceinline__ void g1_load(uint32_t sA, uint32_t sB, int m0, int n0,
                                        int kt, int st, int tid)
{
    const int p = kt >> 5, cc = kt & 31;
    // A: 128 rows x 64B; 512 threads x 16B
    {
        const int row = tid >> 2, part = tid & 3;
        const int sec = (p == 1) ? 1 : 0;               // a: a1, a2', a1
        const __half* g = g_A1H + (size_t)(m0 + row) * 2048 + sec * 1024 + cc * 32 + part * 8;
        CP16(sA + st * AST1 + row * RB1 + part * 16, g);
    }
    // B: 64 rows x 64B; first 256 threads x 16B
    if (tid < 256) {
        const int row = tid >> 2, part = tid & 3;
        const int sec = (p == 0) ? 1 : 0;               // b: b2', b1, b1
        const __half* g = g_B1H + (size_t)(n0 + row) * 2048 + sec * 1024 + cc * 32 + part * 8;
        CP16(sB + st * BST1 + row * RB1 + part * 16, g);
    }
}

__global__ __launch_bounds__(512, 2)
void gemm1_lif_kernel(const float* __restrict__ b1, const float* __restrict__ v0,
                      const float* __restrict__ i0, const float* __restrict__ tau_mem,
                      const float* __restrict__ tau_syn, const float* __restrict__ v_thresh,
                      const float* __restrict__ v_reset, const int* __restrict__ tsteps,
                      float* __restrict__ spikes)
{
    extern __shared__ __align__(128) char smem[];
    const uint32_t sA = smem_u32(smem);
    const uint32_t sB = sA + G1_STAGES * AST1;
    const uint32_t sM = sB + G1_STAGES * BST1;   // masters: [16][512] floats

    const int tid = threadIdx.x, lane = tid & 31, wid = tid >> 5;
    const int wm = wid & 3, wn = wid >> 2;             // 4(m) x 4(n), warp tile 32x16
    const int g = lane >> 2, tq = lane & 3;
    const int mi = lane >> 3, r8 = lane & 7;
    const int m0 = blockIdx.y * 128, n0 = blockIdx.x * 64;

    const uint32_t aoff = (uint32_t)(((mi & 1) * 8 + r8) * RB1 + (mi >> 1) * 16);
    const uint32_t boff = (uint32_t)(((mi >> 1) * 8 + r8) * RB1 + (mi & 1) * 16);

    float tacc[2][2][4];    // tensor-core temp accumulators (16 regs)
#pragma unroll
    for (int a = 0; a < 2; a++)
#pragma unroll
        for (int b = 0; b < 2; b++)
#pragma unroll
            for (int c = 0; c < 4; c++) tacc[a][b][c] = 0.0f;

    g1_load(sA, sB, m0, n0, 0, 0, tid); CP_COMMIT();
    g1_load(sA, sB, m0, n0, 1, 1, tid); CP_COMMIT();
    g1_load(sA, sB, m0, n0, 2, 2, tid); CP_COMMIT();
    g1_load(sA, sB, m0, n0, 3, 3, tid); CP_COMMIT();

    int st = 4;  // next stage slot to fill
    for (int kt = 0; kt < G1_CHUNKS; kt++) {
        const int buf = kt % G1_STAGES;
        CP_WAIT3();
        __syncthreads();
        if (kt + 4 < G1_CHUNKS) {
            g1_load(sA, sB, m0, n0, kt + 4, st, tid);
            if (++st == G1_STAGES) st = 0;
        }
        CP_COMMIT();

        const uint32_t Ab = sA + buf * AST1 + (wm * 32) * RB1 + aoff;
        const uint32_t Bb = sB + buf * BST1 + (wn * 16) * RB1 + boff;
#pragma unroll
        for (int ks = 0; ks < 2; ks++) {
            uint32_t af[2][4], bfr[4];
            LDSM4(af[0], Ab + ks * 32);
            LDSM4(af[1], Ab + 16 * RB1 + ks * 32);
            LDSM4(bfr,   Bb + ks * 32);
#pragma unroll
            for (int mt = 0; mt < 2; mt++)
#pragma unroll
                for (int nt = 0; nt < 2; nt++)
                    mma_f16(tacc[mt][nt], af[mt], &bfr[nt * 2]);
        }
        // Drains into smem masters (transposed [16][512], conflict-free):
        //   kt==63: store corrections x 2^-12 (initializes masters)
        //   kt>63 odd: accumulate a1b1 (64-k chains)
        if (kt == 63) {
#pragma unroll
            for (int mt = 0; mt < 2; mt++)
#pragma unroll
                for (int nt = 0; nt < 2; nt++)
#pragma unroll
                    for (int c = 0; c < 4; c++) {
                        const int i = mt * 8 + nt * 4 + c;
                        const float v = tacc[mt][nt][c] * (1.0f / 4096.0f);
                        asm volatile("st.shared.f32 [%0], %1;" :: "r"(sM + i * 2048 + tid * 4), "f"(v));
                        tacc[mt][nt][c] = 0.0f;
                    }
        } else if (kt > 63 && (kt & 1)) {
#pragma unroll
            for (int mt = 0; mt < 2; mt++)
#pragma unroll
                for (int nt = 0; nt < 2; nt++)
#pragma unroll
                    for (int c = 0; c < 4; c++) {
                        const int i = mt * 8 + nt * 4 + c;
                        const uint32_t ad = sM + i * 2048 + tid * 4;
                        float v;
                        asm volatile("ld.shared.f32 %0, [%1];" : "=f"(v) : "r"(ad));
                        v += tacc[mt][nt][c];
                        asm volatile("st.shared.f32 [%0], %1;" :: "r"(ad), "f"(v));
                        tacc[mt][nt][c] = 0.0f;
                    }
        }
    }
    // C frag: c0=(g,2tq) c1=(g,2tq+1) c2=(g+8,2tq) c3=(g+8,2tq+1)

    // -------------------- fused LIF epilogue --------------------
    const float km  = 1.0f / tau_mem[0];
    const float kss = 1.0f / tau_syn[0];
    const float vth = v_thresh[0];
    const float vre = v_reset[0];
    const int   T   = tsteps[0];
    const float invT = 1.0f / (float)T;

#pragma unroll
    for (int mt = 0; mt < 2; mt++) {
#pragma unroll
        for (int rs = 0; rs < 2; rs++) {
            const int gm = m0 + wm * 32 + mt * 16 + g + rs * 8;
            float cur[4], vv[4], ii[4], cnt[4];
#pragma unroll
            for (int nt = 0; nt < 2; nt++) {
                const int gc = n0 + wn * 16 + nt * 8 + 2 * tq;
                const size_t off = (size_t)gm * HDIM + gc;
                const float2 v2 = __ldcs(reinterpret_cast<const float2*>(v0 + off));
                const float2 i2 = __ldcs(reinterpret_cast<const float2*>(i0 + off));
#pragma unroll
                for (int cj = 0; cj < 2; cj++) {
                    const int i = mt * 8 + nt * 4 + rs * 2 + cj;
                    float ms;
                    asm volatile("ld.shared.f32 %0, [%1];" : "=f"(ms) : "r"(sM + i * 2048 + tid * 4));
                    cur[2 * nt + cj] = (ms + __ldg(b1 + gc + cj)) * invT;
                }
                vv[2 * nt] = v2.x; vv[2 * nt + 1] = v2.y;
                ii[2 * nt] = i2.x; ii[2 * nt + 1] = i2.y;
                cnt[2 * nt] = 0.0f; cnt[2 * nt + 1] = 0.0f;
            }
            for (int t = 0; t < T; t++) {
#pragma unroll
                for (int j = 0; j < 4; j++) {
                    ii[j] = ii[j] - kss * ii[j] + cur[j];
                    vv[j] = vv[j] - km  * vv[j] + ii[j];
                    if (vv[j] >= vth) { cnt[j] += 1.0f; vv[j] = vre; }
                }
            }
#pragma unroll
            for (int nt = 0; nt < 2; nt++) {
                const int gc = n0 + wn * 16 + nt * 8 + 2 * tq;
                float2 s2; s2.x = cnt[2 * nt]; s2.y = cnt[2 * nt + 1];
                __stcs(reinterpret_cast<float2*>(spikes + (size_t)gm * HDIM + gc), s2);
                __half2 sh;
                sh.x = __float2half_rn(cnt[2 * nt]);       // exact: small ints
                sh.y = __float2half_rn(cnt[2 * nt + 1]);
                *reinterpret_cast<__half2*>(g_SH + (size_t)gm * HDIM + gc) = sh;
            }
        }
    }
}

// ------------------------------ GEMM2 --------------------------------------
// out = spikes_fp16 @ W2_fp16^T + b2 (single product, K=2048, 64 chunks).
// Tile 64(M)x64(N), 256 threads, warp grid 4(m)x2(n), warp tile 16x32.
// BK=32, 4 stages, wait_group 2. grid 256 CTAs -> ~4 CTAs/SM, single wave.
#define G2_CHUNKS 64
#define AST2 5120    // 64 rows * 80B per stage
#define BST2 5120    // 64 rows * 80B per stage

__device__ __forceinline__ void g2_load(uint32_t sA, uint32_t sB, int m0, int n0,
                                        int kt, int st, int tid)
{
    const int row = tid >> 2, part = tid & 3;   // 16B per thread per matrix
    {
        const __half* g = g_SH + (size_t)(m0 + row) * HDIM + kt * 32 + part * 8;
        CP16(sA + st * AST2 + row * 80 + part * 16, g);
    }
    {
        const __half* g = g_W2H + (size_t)(n0 + row) * HDIM + kt * 32 + part * 8;
        CP16(sB + st * BST2 + row * 80 + part * 16, g);
    }
}

__global__ __launch_bounds__(256)
void gemm2_kernel(const float* __restrict__ b2, float* __restrict__ out)
{
    extern __shared__ __align__(128) char smem2[];
    const uint32_t sA = smem_u32(smem2);
    const uint32_t sB = sA + 4 * AST2;

    const int tid = threadIdx.x, lane = tid & 31, wid = tid >> 5;
    const int wm = wid & 3, wn = wid >> 2;             // 4(m) x 2(n), warp tile 16x32
    const int g = lane >> 2, tq = lane & 3;
    const int mi = lane >> 3, r8 = lane & 7;
    const int m0 = blockIdx.y * 64, n0 = blockIdx.x * 64;

    const uint32_t aoff = (uint32_t)(((mi & 1) * 8 + r8) * 80 + (mi >> 1) * 16);
    const uint32_t boff = (uint32_t)(((mi >> 1) * 8 + r8) * 80 + (mi & 1) * 16);

    float acc[4][4];
#pragma unroll
    for (int b = 0; b < 4; b++)
#pragma unroll
        for (int c = 0; c < 4; c++) acc[b][c] = 0.0f;

    g2_load(sA, sB, m0, n0, 0, 0, tid); CP_COMMIT();
    g2_load(sA, sB, m0, n0, 1, 1, tid); CP_COMMIT();
    g2_load(sA, sB, m0, n0, 2, 2, tid); CP_COMMIT();

    for (int kt = 0; kt < G2_CHUNKS; kt++) {
        const int buf = kt & 3;
        CP_WAIT2();
        __syncthreads();
        if (kt + 3 < G2_CHUNKS) g2_load(sA, sB, m0, n0, kt + 3, (kt + 3) & 3, tid);
        CP_COMMIT();

        const uint32_t Ab = sA + buf * AST2 + (wm * 16) * 80 + aoff;
        const uint32_t Bb = sB + buf * BST2 + (wn * 32) * 80 + boff;
#pragma unroll
        for (int ks = 0; ks < 2; ks++) {
            uint32_t af[4], bfr[2][4];
            LDSM4(af, Ab + ks * 32);
#pragma unroll
            for (int np = 0; np < 2; np++) LDSM4(bfr[np], Bb + np * 16 * 80 + ks * 32);
#pragma unroll
            for (int nt = 0; nt < 4; nt++)
                mma_f16(acc[nt], af, &bfr[nt >> 1][(nt & 1) * 2]);
        }
    }

#pragma unroll
    for (int rs = 0; rs < 2; rs++) {
        const int gm = m0 + wm * 16 + g + rs * 8;
#pragma unroll
        for (int nt = 0; nt < 4; nt++) {
            const int gc = n0 + wn * 32 + nt * 8 + 2 * tq;
            float2 o2;
            o2.x = acc[nt][rs * 2 + 0] + __ldg(b2 + gc);
            o2.y = acc[nt][rs * 2 + 1] + __ldg(b2 + gc + 1);
            __stcs(reinterpret_cast<float2*>(out + (size_t)gm * ODIM + gc), o2);
        }
    }
}

// ---------------------------------------------------------------------------
extern "C" void kernel_launch(void* const* d_in, const int* in_sizes, int n_in,
                              void* d_out, int out_size)
{
    const float* x        = (const float*)d_in[0];
    const float* W1       = (const float*)d_in[1];
    const float* b1       = (const float*)d_in[2];
    const float* W2       = (const float*)d_in[3];
    const float* b2       = (const float*)d_in[4];
    const float* tau_mem  = (const float*)d_in[5];
    const float* tau_syn  = (const float*)d_in[6];
    const float* v_thresh = (const float*)d_in[7];
    const float* v_reset  = (const float*)d_in[8];
    const float* v0       = (const float*)d_in[9];
    const float* i0       = (const float*)d_in[10];
    const int*   tsteps   = (const int*)d_in[11];

    float* out    = (float*)d_out;
    float* spikes = out + (size_t)BDIM * ODIM;

    const int smem2 = 4 * (AST2 + BST2);     // 40960  -> ~4 CTAs/SM
    cudaFuncSetAttribute(gemm1_lif_kernel, cudaFuncAttributeMaxDynamicSharedMemorySize, SMEM1);
    cudaFuncSetAttribute(gemm2_kernel,     cudaFuncAttributeMaxDynamicSharedMemorySize, smem2);

    split_all_kernel<<<2048, 256>>>(x, W1, W2);

    dim3 g1(HDIM / 64, BDIM / 128);    // 32 x 32 = 1024 CTAs
    gemm1_lif_kernel<<<g1, 512, SMEM1>>>(b1, v0, i0, tau_mem, tau_syn,
                                         v_thresh, v_reset, tsteps, spikes);

    dim3 g2(ODIM / 64, BDIM / 64);     // 4 x 64 = 256 CTAs
    gemm2_kernel<<<g2, 256, smem2>>>(b2, out);
}